// round 8
// baseline (speedup 1.0000x reference)
#include <cuda_runtime.h>
#include <math.h>

#define B_  8
#define N_  2048
#define H_  4
#define DM  256
#define DH  64
#define OUT_ELEMS ((size_t)B_ * N_ * DM)

// Scratch (device globals: allocation-free rule)
__device__ float g_q [(size_t)B_*H_*N_*DH];   // [B,H,N,64]
__device__ float g_kr[(size_t)B_*H_*N_*DH];   // [B,H,N,64]  (k_proj + r_proj, both biases)
__device__ float g_v [(size_t)B_*H_*N_*DH];   // [B,H,N,64]
__device__ float g_x [(size_t)B_*N_*DM];      // [B,N,256] concat-head attention output

// ---------------------------------------------------------------------------
// Kernel 1: per-head projections.
//   blockIdx.z: 0 -> q = Q@Wq + bq ; 1 -> kr = K@Wk + R@Wr + bk + br ; 2 -> v
//   blockIdx.y: head ; blockIdx.x: 64-row tile of the 16384 (b,n) rows
// 64x64x16 tiling, 256 threads, 4x4 microtiles.
// ---------------------------------------------------------------------------
__global__ __launch_bounds__(256) void proj_kernel(
    const float* __restrict__ Q, const float* __restrict__ K,
    const float* __restrict__ V, const float* __restrict__ R,
    const float* __restrict__ Wq, const float* __restrict__ bq,
    const float* __restrict__ Wk, const float* __restrict__ bk,
    const float* __restrict__ Wv, const float* __restrict__ bv,
    const float* __restrict__ Wr, const float* __restrict__ br)
{
    const int which = blockIdx.z;
    const int h     = blockIdx.y;
    const int row0  = blockIdx.x * 64;
    const int t  = threadIdx.x;
    const int tx = t & 15;        // 0..15 -> 4 output cols
    const int ty = t >> 4;        // 0..15 -> 4 output rows

    __shared__ float As[16][64];  // [k][row]
    __shared__ float Bs[16][64];  // [k][col]

    const float* A0; const float* W0;
    const float* A1 = nullptr; const float* W1 = nullptr;
    float* Cout;
    if (which == 0)      { A0 = Q; W0 = Wq; Cout = g_q;  }
    else if (which == 1) { A0 = K; W0 = Wk; A1 = R; W1 = Wr; Cout = g_kr; }
    else                 { A0 = V; W0 = Wv; Cout = g_v;  }

    float acc[4][4];
    #pragma unroll
    for (int r = 0; r < 4; ++r)
        #pragma unroll
        for (int c = 0; c < 4; ++c) acc[r][c] = 0.f;

    const int npass = (which == 1) ? 2 : 1;
    for (int pass = 0; pass < npass; ++pass) {
        const float* A = pass ? A1 : A0;
        const float* W = pass ? W1 : W0;
        for (int k0 = 0; k0 < DM; k0 += 16) {
            // A tile: 64 rows x 16 k, transposed store
            {
                const int ar = t >> 2, ac = (t & 3) * 4;
                float4 a4 = *(const float4*)(A + (size_t)(row0 + ar) * DM + k0 + ac);
                As[ac + 0][ar] = a4.x; As[ac + 1][ar] = a4.y;
                As[ac + 2][ar] = a4.z; As[ac + 3][ar] = a4.w;
            }
            // W tile: 16 k x 64 cols.  W[h, d, k] layout: [H, DM, DH]
            {
                const int wd = t >> 4, wc = (t & 15) * 4;
                *(float4*)&Bs[wd][wc] =
                    *(const float4*)(W + (size_t)h * DM * DH + (size_t)(k0 + wd) * DH + wc);
            }
            __syncthreads();
            #pragma unroll
            for (int kk = 0; kk < 16; ++kk) {
                float4 af = *(float4*)&As[kk][ty * 4];
                float4 bf = *(float4*)&Bs[kk][tx * 4];
                float a[4] = {af.x, af.y, af.z, af.w};
                float b[4] = {bf.x, bf.y, bf.z, bf.w};
                #pragma unroll
                for (int r = 0; r < 4; ++r)
                    #pragma unroll
                    for (int c = 0; c < 4; ++c) acc[r][c] += a[r] * b[c];
            }
            __syncthreads();
        }
    }

    // bias + store to head-major scratch [B,H,N,64]
    const float* bA = (which == 0) ? bq : (which == 1) ? bk : bv;
    float bias[4];
    #pragma unroll
    for (int c = 0; c < 4; ++c) {
        bias[c] = bA[h * DH + tx * 4 + c];
        if (which == 1) bias[c] += br[h * DH + tx * 4 + c];
    }
    #pragma unroll
    for (int r = 0; r < 4; ++r) {
        const int row = row0 + ty * 4 + r;       // global (b,n) row
        const int b   = row >> 11;               // /2048
        const int n   = row & (N_ - 1);
        float4 o = make_float4(acc[r][0] + bias[0], acc[r][1] + bias[1],
                               acc[r][2] + bias[2], acc[r][3] + bias[3]);
        *(float4*)(Cout + ((size_t)(b * H_ + h) * N_ + n) * DH + tx * 4) = o;
    }
}

// ---------------------------------------------------------------------------
// Kernel 2: flash attention per (b,h) with 64-query tiles.
//   - scale (1/8) folded into the q smem tile, so S frags ARE the scores
//   - scores streamed to d_out (pre-softmax, scaled) with float4 stores
//   - online softmax, row reductions via shfl_xor over the 16 lanes of a row
//   - 48 KB STATIC smem: P reuses the dead k_sT buffer
//   - P@V reads P ROW-major (P[i][j]) — fp32 float4 loads, broadcast across tx
// ---------------------------------------------------------------------------
__global__ __launch_bounds__(256) void attn_kernel(float* __restrict__ scores_out)
{
    __shared__ float sm[12288];    // 48 KB
    float* q_sT = sm;              // [64 d][64 i]
    float* k_sT = sm + 4096;       // [64 d][64 j], reused as P [64 i][64 j]
    float* v_s  = sm + 8192;       // [64 j][64 c]

    const int qt = blockIdx.x;     // 0..31 query tile
    const int bh = blockIdx.y;     // 0..31 (b*H + h)
    const int t  = threadIdx.x;
    const int tx = t & 15, ty = t >> 4;
    const int tx4 = tx * 4, ty4 = ty * 4;

    const float* qptr  = g_q  + ((size_t)bh * N_ + (size_t)qt * 64) * DH;
    const float* krptr = g_kr + (size_t)bh * N_ * DH;
    const float* vptr  = g_v  + (size_t)bh * N_ * DH;
    float* sc = scores_out + (size_t)bh * N_ * N_ + (size_t)qt * 64 * N_;

    // load q tile, transposed + pre-scaled by 1/sqrt(64) = 0.125 (exact)
    {
        const int i = t >> 2;
        #pragma unroll
        for (int rep = 0; rep < 4; ++rep) {
            const int col = (t & 3) * 4 + rep * 16;
            float4 a = *(const float4*)(qptr + (size_t)i * DH + col);
            q_sT[(col + 0) * 64 + i] = a.x * 0.125f;
            q_sT[(col + 1) * 64 + i] = a.y * 0.125f;
            q_sT[(col + 2) * 64 + i] = a.z * 0.125f;
            q_sT[(col + 3) * 64 + i] = a.w * 0.125f;
        }
    }
    __syncthreads();

    float m_i[4], l_i[4], o_acc[4][4];
    #pragma unroll
    for (int r = 0; r < 4; ++r) {
        m_i[r] = -INFINITY; l_i[r] = 0.f;
        #pragma unroll
        for (int c = 0; c < 4; ++c) o_acc[r][c] = 0.f;
    }

    for (int kt = 0; kt < N_ / 64; ++kt) {
        // load kr (transposed) and v (natural) tiles
        {
            const float* kp = krptr + (size_t)kt * 64 * DH;
            const float* vp = vptr  + (size_t)kt * 64 * DH;
            const int j = t >> 2;
            #pragma unroll
            for (int rep = 0; rep < 4; ++rep) {
                const int col = (t & 3) * 4 + rep * 16;
                float4 a = *(const float4*)(kp + (size_t)j * DH + col);
                k_sT[(col + 0) * 64 + j] = a.x;
                k_sT[(col + 1) * 64 + j] = a.y;
                k_sT[(col + 2) * 64 + j] = a.z;
                k_sT[(col + 3) * 64 + j] = a.w;
                *(float4*)&v_s[j * 64 + col] = *(const float4*)(vp + (size_t)j * DH + col);
            }
        }
        __syncthreads();

        // S = q_tile @ kr_tile^T  (scale already in q)
        float s[4][4];
        #pragma unroll
        for (int r = 0; r < 4; ++r)
            #pragma unroll
            for (int c = 0; c < 4; ++c) s[r][c] = 0.f;
        #pragma unroll 8
        for (int d = 0; d < 64; ++d) {
            float4 qa = *(float4*)&q_sT[d * 64 + ty4];
            float4 kb = *(float4*)&k_sT[d * 64 + tx4];
            float a[4] = {qa.x, qa.y, qa.z, qa.w};
            float b[4] = {kb.x, kb.y, kb.z, kb.w};
            #pragma unroll
            for (int r = 0; r < 4; ++r)
                #pragma unroll
                for (int c = 0; c < 4; ++c) s[r][c] += a[r] * b[c];
        }

        // stream pre-softmax scaled scores to global
        #pragma unroll
        for (int r = 0; r < 4; ++r) {
            float4 sv = make_float4(s[r][0], s[r][1], s[r][2], s[r][3]);
            *(float4*)(sc + (size_t)(ty4 + r) * N_ + kt * 64 + tx4) = sv;
        }

        // online softmax (rows 4*ty+r split across 16 tx lanes)
        #pragma unroll
        for (int r = 0; r < 4; ++r) {
            float mx = fmaxf(fmaxf(s[r][0], s[r][1]), fmaxf(s[r][2], s[r][3]));
            #pragma unroll
            for (int off = 8; off > 0; off >>= 1)
                mx = fmaxf(mx, __shfl_xor_sync(0xffffffffu, mx, off));
            const float mnew = fmaxf(m_i[r], mx);
            const float corr = __expf(m_i[r] - mnew);
            float rs = 0.f;
            #pragma unroll
            for (int c = 0; c < 4; ++c) {
                float p = __expf(s[r][c] - mnew);
                s[r][c] = p;
                rs += p;
            }
            #pragma unroll
            for (int off = 8; off > 0; off >>= 1)
                rs += __shfl_xor_sync(0xffffffffu, rs, off);
            l_i[r] = l_i[r] * corr + rs;
            m_i[r] = mnew;
            #pragma unroll
            for (int c = 0; c < 4; ++c) o_acc[r][c] *= corr;
        }

        // all threads done reading k_sT -> safe to overwrite with P
        __syncthreads();

        // P -> shared (reusing k_sT, natural [i][j] layout, float4 stores)
        float* p_s = k_sT;
        #pragma unroll
        for (int r = 0; r < 4; ++r) {
            float4 pv = make_float4(s[r][0], s[r][1], s[r][2], s[r][3]);
            *(float4*)&p_s[(ty4 + r) * 64 + tx4] = pv;
        }
        __syncthreads();

        // O += P @ V   (P read ROW-major: o[i][c] += P[i][j] * V[j][c])
        #pragma unroll 4
        for (int j0 = 0; j0 < 64; j0 += 4) {
            float pr[4][4];
            #pragma unroll
            for (int r = 0; r < 4; ++r) {
                float4 p4 = *(float4*)&p_s[(ty4 + r) * 64 + j0];
                pr[r][0] = p4.x; pr[r][1] = p4.y; pr[r][2] = p4.z; pr[r][3] = p4.w;
            }
            #pragma unroll
            for (int jj = 0; jj < 4; ++jj) {
                float4 vv = *(float4*)&v_s[(j0 + jj) * 64 + tx4];
                float vb[4] = {vv.x, vv.y, vv.z, vv.w};
                #pragma unroll
                for (int r = 0; r < 4; ++r)
                    #pragma unroll
                    for (int c = 0; c < 4; ++c) o_acc[r][c] += pr[r][jj] * vb[c];
            }
        }
        __syncthreads();
    }

    // finalize: O /= l, write concat-head layout [B,N,256]
    const int b = bh >> 2;      // bh = b*H + h
    const int h = bh & 3;
    #pragma unroll
    for (int r = 0; r < 4; ++r) {
        const float inv = 1.f / l_i[r];
        const int n = qt * 64 + ty4 + r;
        float4 o = make_float4(o_acc[r][0] * inv, o_acc[r][1] * inv,
                               o_acc[r][2] * inv, o_acc[r][3] * inv);
        *(float4*)(g_x + ((size_t)b * N_ + n) * DM + h * DH + tx4) = o;
    }
}

// ---------------------------------------------------------------------------
// Kernel 3: out = x @ Wo^T + bo     (Wo is [out, in])
// ---------------------------------------------------------------------------
__global__ __launch_bounds__(256) void outproj_kernel(
    float* __restrict__ out, const float* __restrict__ Wo, const float* __restrict__ bo)
{
    const int o0   = blockIdx.y * 64;
    const int row0 = blockIdx.x * 64;
    const int t  = threadIdx.x;
    const int tx = t & 15, ty = t >> 4;

    __shared__ float As[16][64];  // [k][row]
    __shared__ float Bs[16][64];  // [k][ocol]  Bs[d][o] = Wo[o, d]

    float acc[4][4];
    #pragma unroll
    for (int r = 0; r < 4; ++r)
        #pragma unroll
        for (int c = 0; c < 4; ++c) acc[r][c] = 0.f;

    for (int k0 = 0; k0 < DM; k0 += 16) {
        {
            const int ar = t >> 2, ac = (t & 3) * 4;
            float4 a4 = *(const float4*)(g_x + (size_t)(row0 + ar) * DM + k0 + ac);
            As[ac + 0][ar] = a4.x; As[ac + 1][ar] = a4.y;
            As[ac + 2][ar] = a4.z; As[ac + 3][ar] = a4.w;
        }
        {
            const int oc = t >> 2, d4 = (t & 3) * 4;
            float4 w = *(const float4*)(Wo + (size_t)(o0 + oc) * DM + k0 + d4);
            Bs[d4 + 0][oc] = w.x; Bs[d4 + 1][oc] = w.y;
            Bs[d4 + 2][oc] = w.z; Bs[d4 + 3][oc] = w.w;
        }
        __syncthreads();
        #pragma unroll
        for (int kk = 0; kk < 16; ++kk) {
            float4 af = *(float4*)&As[kk][ty * 4];
            float4 bf = *(float4*)&Bs[kk][tx * 4];
            float a[4] = {af.x, af.y, af.z, af.w};
            float b[4] = {bf.x, bf.y, bf.z, bf.w};
            #pragma unroll
            for (int r = 0; r < 4; ++r)
                #pragma unroll
                for (int c = 0; c < 4; ++c) acc[r][c] += a[r] * b[c];
        }
        __syncthreads();
    }

    float bias[4];
    #pragma unroll
    for (int c = 0; c < 4; ++c) bias[c] = bo[o0 + tx * 4 + c];
    #pragma unroll
    for (int r = 0; r < 4; ++r) {
        const int row = row0 + ty * 4 + r;
        float4 o = make_float4(acc[r][0] + bias[0], acc[r][1] + bias[1],
                               acc[r][2] + bias[2], acc[r][3] + bias[3]);
        *(float4*)(out + (size_t)row * DM + o0 + tx * 4) = o;
    }
}

// ---------------------------------------------------------------------------
extern "C" void kernel_launch(void* const* d_in, const int* in_sizes, int n_in,
                              void* d_out, int out_size)
{
    const float* Q  = (const float*)d_in[0];
    const float* K  = (const float*)d_in[1];
    const float* V  = (const float*)d_in[2];
    const float* R  = (const float*)d_in[3];
    const float* Wq = (const float*)d_in[4];
    const float* bq = (const float*)d_in[5];
    const float* Wk = (const float*)d_in[6];
    const float* bk = (const float*)d_in[7];
    const float* Wv = (const float*)d_in[8];
    const float* bv = (const float*)d_in[9];
    const float* Wr = (const float*)d_in[10];
    const float* br = (const float*)d_in[11];
    const float* Wo = (const float*)d_in[12];
    const float* bo = (const float*)d_in[13];

    float* out    = (float*)d_out;            // [B,N,256]
    float* scores = out + OUT_ELEMS;          // [B,H,N,N]

    // 1) projections: z = {q, kr, v}
    proj_kernel<<<dim3((B_ * N_) / 64, H_, 3), 256>>>(
        Q, K, V, R, Wq, bq, Wk, bk, Wv, bv, Wr, br);

    // 2) flash attention + scores streaming (48 KB static smem)
    attn_kernel<<<dim3(N_ / 64, B_ * H_), 256>>>(scores);

    // 3) output projection
    outproj_kernel<<<dim3((B_ * N_) / 64, DM / 64), 256>>>(out, Wo, bo);
}